// round 15
// baseline (speedup 1.0000x reference)
#include <cuda_runtime.h>
#include <cuda_bf16.h>
#include <math.h>
#include <stdint.h>

// Problem constants
#define NB   8
#define T    2048
#define NE   1024
#define H    128
#define BT   (NB * T)   // 16384

// ---------------------------------------------------------------------------
// Device-global scratch (no allocs allowed)
// ---------------------------------------------------------------------------
__device__ __nv_bfloat16 g_qh[BT * H];             // q hi (pre-scaled 1/32)
__device__ __nv_bfloat16 g_ql[BT * H];             // q lo
__device__ __nv_bfloat16 g_kh[BT * H];             // k hi
__device__ __nv_bfloat16 g_kl[BT * H];             // k lo
__device__ __nv_bfloat16 g_vth[NB * H * T];        // v^T hi: [b][h][t]
__device__ __nv_bfloat16 g_vtl[NB * H * T];        // v^T lo

__device__ __nv_bfloat16 g_xh[BT * NE];            // x hi split
__device__ __nv_bfloat16 g_xl[BT * NE];            // x lo split
__device__ __nv_bfloat16 g_wth[3 * H * NE];        // W^T hi: [mat][n][k]
__device__ __nv_bfloat16 g_wtl[3 * H * NE];        // W^T lo

// ---------------------------------------------------------------------------
// PTX helpers
// ---------------------------------------------------------------------------
__device__ __forceinline__ void mma16816(float* d,
                                         const uint32_t* a,
                                         const uint32_t* b)
{
    asm volatile(
        "mma.sync.aligned.m16n8k16.row.col.f32.bf16.bf16.f32 "
        "{%0,%1,%2,%3}, {%4,%5,%6,%7}, {%8,%9}, {%0,%1,%2,%3};"
        : "+f"(d[0]), "+f"(d[1]), "+f"(d[2]), "+f"(d[3])
        : "r"(a[0]), "r"(a[1]), "r"(a[2]), "r"(a[3]),
          "r"(b[0]), "r"(b[1]));
}

__device__ __forceinline__ uint32_t smem_u32(const void* p) {
    return (uint32_t)__cvta_generic_to_shared(p);
}

__device__ __forceinline__ void cp16(uint32_t saddr, const void* gptr) {
    asm volatile("cp.async.cg.shared.global [%0], [%1], 16;"
                 :: "r"(saddr), "l"(__cvta_generic_to_global(gptr)) : "memory");
}

#define CP_COMMIT()   asm volatile("cp.async.commit_group;" ::: "memory")
#define CP_WAIT_ALL() asm volatile("cp.async.wait_group 0;" ::: "memory")
#define CP_WAIT_1()   asm volatile("cp.async.wait_group 1;" ::: "memory")
#define BAR_GRP(id)   asm volatile("bar.sync %0, 128;" :: "r"(id) : "memory")

// split a float pair into packed bf16x2 hi and lo
__device__ __forceinline__ uint32_t pack_split(float x, float y, uint32_t& lo)
{
    __nv_bfloat16 hx = __float2bfloat16_rn(x);
    __nv_bfloat16 hy = __float2bfloat16_rn(y);
    __nv_bfloat162 hp(hx, hy);
    __nv_bfloat162 lp(__float2bfloat16_rn(x - __bfloat162float(hx)),
                      __float2bfloat16_rn(y - __bfloat162float(hy)));
    lo = *(uint32_t*)&lp;
    return *(uint32_t*)&hp;
}

// ---------------------------------------------------------------------------
// Prep: split x into bf16 hi/lo — 4x MLP version
// ---------------------------------------------------------------------------
__global__ __launch_bounds__(256)
void split_x_kernel(const float* __restrict__ x)
{
    const int base = blockIdx.x * 1024 + threadIdx.x;   // float4 index
    float4 v[4];
#pragma unroll
    for (int j = 0; j < 4; j++)
        v[j] = ((const float4*)x)[base + j * 256];

    __nv_bfloat162* ph = (__nv_bfloat162*)g_xh;
    __nv_bfloat162* pl = (__nv_bfloat162*)g_xl;
#pragma unroll
    for (int j = 0; j < 4; j++) {
        const int i = base + j * 256;
        __nv_bfloat16 h0 = __float2bfloat16_rn(v[j].x);
        __nv_bfloat16 h1 = __float2bfloat16_rn(v[j].y);
        __nv_bfloat16 h2 = __float2bfloat16_rn(v[j].z);
        __nv_bfloat16 h3 = __float2bfloat16_rn(v[j].w);
        __nv_bfloat16 l0 = __float2bfloat16_rn(v[j].x - __bfloat162float(h0));
        __nv_bfloat16 l1 = __float2bfloat16_rn(v[j].y - __bfloat162float(h1));
        __nv_bfloat16 l2 = __float2bfloat16_rn(v[j].z - __bfloat162float(h2));
        __nv_bfloat16 l3 = __float2bfloat16_rn(v[j].w - __bfloat162float(h3));
        ph[2 * i]     = __nv_bfloat162(h0, h1);
        ph[2 * i + 1] = __nv_bfloat162(h2, h3);
        pl[2 * i]     = __nv_bfloat162(l0, l1);
        pl[2 * i + 1] = __nv_bfloat162(l2, l3);
    }
}

// ---------------------------------------------------------------------------
// Prep: transpose + split W (3 matrices) -> [mat][n][k] bf16 hi/lo
// ---------------------------------------------------------------------------
__global__ __launch_bounds__(256)
void split_w_kernel(const float* __restrict__ Wq,
                    const float* __restrict__ Wk,
                    const float* __restrict__ Wv)
{
    int mat = blockIdx.y;
    const float* W = (mat == 0) ? Wq : (mat == 1) ? Wk : Wv;
    int i = blockIdx.x * 256 + threadIdx.x;
    int k = i >> 7;
    int n = i & 127;
    float w = W[i];
    __nv_bfloat16 hi = __float2bfloat16_rn(w);
    __nv_bfloat16 lo = __float2bfloat16_rn(w - __bfloat162float(hi));
    size_t o = (size_t)mat * (H * NE) + (size_t)n * NE + k;
    g_wth[o] = hi;
    g_wtl[o] = lo;
}

// ---------------------------------------------------------------------------
// QKV GEMM via mma.sync (bf16 hi/lo split, fp32 accum).
// 256-row CTA tile, 512 threads (16 warps = 8m x 2n, warp = 32m x 64n),
// KC=64, cp.async DOUBLE-BUFFERED. 4 warps/SMSP, grid 192 CTAs (1.3 waves).
// mat==2 epilogue: in-kernel transpose+split of v -> g_vth/g_vtl.
// ---------------------------------------------------------------------------
#define KC        64
#define TSTRIDE   72
#define GM_TILE   256
#define GTHREADS  512
#define TILE_X_BF (GM_TILE * TSTRIDE)            // 18432 elems
#define TILE_W_BF (128 * TSTRIDE)                // 9216 elems
#define GBUF_ELEMS (2 * TILE_X_BF + 2 * TILE_W_BF)   // 55296
#define GEMM_SMEM_BYTES (2 * GBUF_ELEMS * 2)         // 221184

extern __shared__ __nv_bfloat16 gsm[];

__device__ __forceinline__ void gemm_stage(uint32_t sb, int buf, int m0,
                                           const __nv_bfloat16* wh_base,
                                           const __nv_bfloat16* wl_base,
                                           int k0, int tid)
{
    const uint32_t base = sb + buf * (GBUF_ELEMS * 2);
    // x tiles: 256 rows x 64 bf16 (8 uint4 per row)
#pragma unroll
    for (int it = 0; it < 4; it++) {
        int idx = it * 512 + tid;                // 0..2047
        int r  = idx >> 3;
        int c8 = (idx & 7) * 8;
        size_t xs = (size_t)(m0 + r) * NE + k0 + c8;
        uint32_t dsto = (r * TSTRIDE + c8) * 2;
        cp16(base + dsto, g_xh + xs);
        cp16(base + TILE_X_BF * 2 + dsto, g_xl + xs);
    }
    // W tiles: 128 rows x 64 bf16
#pragma unroll
    for (int it = 0; it < 2; it++) {
        int idx = it * 512 + tid;                // 0..1023
        int r  = idx >> 3;
        int c8 = (idx & 7) * 8;
        size_t ws = (size_t)r * NE + k0 + c8;
        uint32_t dsto = (r * TSTRIDE + c8) * 2;
        cp16(base + 2 * TILE_X_BF * 2 + dsto, wh_base + ws);
        cp16(base + 2 * TILE_X_BF * 2 + TILE_W_BF * 2 + dsto, wl_base + ws);
    }
}

__global__ __launch_bounds__(GTHREADS, 1)
void qkv_mma_kernel()
{
    const uint32_t sb = smem_u32(gsm);

    const int tid = threadIdx.x;
    const int wid = tid >> 5;                    // 0..15
    const int lid = tid & 31;
    const int g   = lid >> 2;
    const int t   = lid & 3;

    const int m0  = blockIdx.x * GM_TILE;
    const int mat = blockIdx.y;
    const int wm  = (wid >> 1) * 32;             // 0..224
    const int wn  = (wid & 1) * 64;

    const __nv_bfloat16* wh_base = g_wth + (size_t)mat * (H * NE);
    const __nv_bfloat16* wl_base = g_wtl + (size_t)mat * (H * NE);

    float acc[2][8][4];
#pragma unroll
    for (int mi = 0; mi < 2; mi++)
#pragma unroll
        for (int ni = 0; ni < 8; ni++)
#pragma unroll
            for (int c = 0; c < 4; c++) acc[mi][ni][c] = 0.f;

    gemm_stage(sb, 0, m0, wh_base, wl_base, 0, tid);
    CP_COMMIT();

    for (int kc = 0; kc < 16; kc++) {
        if (kc < 15) {
            gemm_stage(sb, (kc + 1) & 1, m0, wh_base, wl_base, (kc + 1) * KC, tid);
            CP_COMMIT();
            CP_WAIT_1();
        } else {
            CP_WAIT_ALL();
        }
        __syncthreads();

        const __nv_bfloat16* Axh = gsm + (kc & 1) * GBUF_ELEMS;
        const __nv_bfloat16* Axl = Axh + TILE_X_BF;
        const __nv_bfloat16* Bwh = Axl + TILE_X_BF;
        const __nv_bfloat16* Bwl = Bwh + TILE_W_BF;

#pragma unroll
        for (int ks = 0; ks < 4; ks++) {
            const int kk = ks * 16;
            uint32_t ah[2][4], al[2][4];
#pragma unroll
            for (int mi = 0; mi < 2; mi++) {
                int r = wm + mi * 16;
                ah[mi][0] = *(const uint32_t*)&Axh[(r + g    ) * TSTRIDE + kk + 2 * t    ];
                ah[mi][1] = *(const uint32_t*)&Axh[(r + g + 8) * TSTRIDE + kk + 2 * t    ];
                ah[mi][2] = *(const uint32_t*)&Axh[(r + g    ) * TSTRIDE + kk + 2 * t + 8];
                ah[mi][3] = *(const uint32_t*)&Axh[(r + g + 8) * TSTRIDE + kk + 2 * t + 8];
                al[mi][0] = *(const uint32_t*)&Axl[(r + g    ) * TSTRIDE + kk + 2 * t    ];
                al[mi][1] = *(const uint32_t*)&Axl[(r + g + 8) * TSTRIDE + kk + 2 * t    ];
                al[mi][2] = *(const uint32_t*)&Axl[(r + g    ) * TSTRIDE + kk + 2 * t + 8];
                al[mi][3] = *(const uint32_t*)&Axl[(r + g + 8) * TSTRIDE + kk + 2 * t + 8];
            }
            // block-of-4 n-tiles: 8 independent MMAs between accumulator reuse
#pragma unroll
            for (int nb = 0; nb < 2; nb++) {
                uint32_t bh[4][2], bl[4][2];
#pragma unroll
                for (int j = 0; j < 4; j++) {
                    int nr = wn + (nb * 4 + j) * 8 + g;
                    bh[j][0] = *(const uint32_t*)&Bwh[nr * TSTRIDE + kk + 2 * t    ];
                    bh[j][1] = *(const uint32_t*)&Bwh[nr * TSTRIDE + kk + 2 * t + 8];
                    bl[j][0] = *(const uint32_t*)&Bwl[nr * TSTRIDE + kk + 2 * t    ];
                    bl[j][1] = *(const uint32_t*)&Bwl[nr * TSTRIDE + kk + 2 * t + 8];
                }
#pragma unroll
                for (int j = 0; j < 4; j++)
#pragma unroll
                    for (int mi = 0; mi < 2; mi++)
                        mma16816(acc[mi][nb * 4 + j], ah[mi], bh[j]);
#pragma unroll
                for (int j = 0; j < 4; j++)
#pragma unroll
                    for (int mi = 0; mi < 2; mi++)
                        mma16816(acc[mi][nb * 4 + j], ah[mi], bl[j]);
#pragma unroll
                for (int j = 0; j < 4; j++)
#pragma unroll
                    for (int mi = 0; mi < 2; mi++)
                        mma16816(acc[mi][nb * 4 + j], al[mi], bh[j]);
            }
        }
        __syncthreads();
    }

    // epilogue
    if (mat == 2) {
        // stage v tile (fp32) to smem, then transposed+split write to g_vt*
        float* ep = (float*)gsm;                 // 256 x 132 fp32 = 135 KB
#pragma unroll
        for (int mi = 0; mi < 2; mi++)
#pragma unroll
            for (int ni = 0; ni < 8; ni++) {
                int lr = wm + mi * 16 + g;
                int c  = wn + ni * 8 + 2 * t;
                ep[lr * 132 + c]           = acc[mi][ni][0];
                ep[lr * 132 + c + 1]       = acc[mi][ni][1];
                ep[(lr + 8) * 132 + c]     = acc[mi][ni][2];
                ep[(lr + 8) * 132 + c + 1] = acc[mi][ni][3];
            }
        __syncthreads();

        const int b  = m0 >> 11;                 // batch
        const int t0 = m0 & 2047;                // t offset within batch
        const int h   = tid & 127;
        const int sel = (tid >> 7) & 1;          // 0 = hi, 1 = lo
        const int rh  = tid >> 8;                // row half 0/1
        __nv_bfloat16* dst = sel ? g_vtl : g_vth;
        __nv_bfloat16* drow = dst + ((size_t)b * H + h) * T + t0 + rh * 128;
#pragma unroll
        for (int j8 = 0; j8 < 16; j8++) {
            union { __nv_bfloat16 bh[8]; uint4 u4; } tmp;
#pragma unroll
            for (int u = 0; u < 8; u++) {
                float v = ep[(rh * 128 + j8 * 8 + u) * 132 + h];
                __nv_bfloat16 hi = __float2bfloat16_rn(v);
                tmp.bh[u] = sel ? __float2bfloat16_rn(v - __bfloat162float(hi))
                                : hi;
            }
            *(uint4*)&drow[j8 * 8] = tmp.u4;
        }
    } else {
        const float sc = (mat == 0) ? 0.03125f : 1.0f;
        __nv_bfloat16* dh = (mat == 0) ? g_qh : g_kh;
        __nv_bfloat16* dl = (mat == 0) ? g_ql : g_kl;
#pragma unroll
        for (int mi = 0; mi < 2; mi++)
#pragma unroll
            for (int ni = 0; ni < 8; ni++) {
                int r0 = m0 + wm + mi * 16 + g;
                int c  = wn + ni * 8 + 2 * t;
                uint32_t lo0, lo1;
                uint32_t hi0 = pack_split(acc[mi][ni][0] * sc, acc[mi][ni][1] * sc, lo0);
                uint32_t hi1 = pack_split(acc[mi][ni][2] * sc, acc[mi][ni][3] * sc, lo1);
                *(uint32_t*)&dh[(size_t)r0 * H + c]       = hi0;
                *(uint32_t*)&dl[(size_t)r0 * H + c]       = lo0;
                *(uint32_t*)&dh[(size_t)(r0 + 8) * H + c] = hi1;
                *(uint32_t*)&dl[(size_t)(r0 + 8) * H + c] = lo1;
            }
    }
}

// ---------------------------------------------------------------------------
// Flash attention: split-K across 2 warp groups (256 threads), plain-LDS
// frag loads, ILP-ordered MMAs (R11 form, verbatim). Group wg handles
// kv-chunks kb ≡ wg (mod 2) in its own buffer; states merged at the end.
// Grid (16, 8), paired q-tiles.
// ---------------------------------------------------------------------------
#define KSTRIDE 136
#define VSTRIDE 72
#define AT_SKH  0
#define AT_SKL  (64 * KSTRIDE)
#define AT_SVH  (2 * 64 * KSTRIDE)
#define AT_SVL  (2 * 64 * KSTRIDE + 128 * VSTRIDE)
#define AT_BUF_ELEMS (2 * 64 * KSTRIDE + 2 * 128 * VSTRIDE)   // 35840
#define AT_SMEM_BYTES (2 * AT_BUF_ELEMS * 2)                  // 143360
#define MSTRIDE 69                                            // merge stride

extern __shared__ __nv_bfloat16 att_sm[];

__device__ __forceinline__ void stage_kv(uint32_t smbase, int buf, int b,
                                         int kv0, int t128)
{
    const __nv_bfloat16* kh  = g_kh  + ((size_t)b * T + kv0) * H;
    const __nv_bfloat16* kl  = g_kl  + ((size_t)b * T + kv0) * H;
    const __nv_bfloat16* vth = g_vth + (size_t)b * H * T + kv0;
    const __nv_bfloat16* vtl = g_vtl + (size_t)b * H * T + kv0;
    const uint32_t base = smbase + buf * (AT_BUF_ELEMS * 2);
#pragma unroll
    for (int it = 0; it < 8; it++) {
        int idx = it * 128 + t128;
        int r  = idx >> 4;
        int c8 = (idx & 15) * 8;
        cp16(base + (AT_SKH + r * KSTRIDE + c8) * 2, kh + (size_t)r * H + c8);
        cp16(base + (AT_SKL + r * KSTRIDE + c8) * 2, kl + (size_t)r * H + c8);
    }
#pragma unroll
    for (int it = 0; it < 8; it++) {
        int idx = it * 128 + t128;
        int r  = idx >> 3;
        int c8 = (idx & 7) * 8;
        cp16(base + (AT_SVH + r * VSTRIDE + c8) * 2, vth + (size_t)r * T + c8);
        cp16(base + (AT_SVL + r * VSTRIDE + c8) * 2, vtl + (size_t)r * T + c8);
    }
}

__global__ __launch_bounds__(256, 1)
void attn_mma_kernel(float* __restrict__ out)
{
    __nv_bfloat16* sm = att_sm;
    const uint32_t smbase = smem_u32(att_sm);
    const int tid  = threadIdx.x;
    const int wg   = tid >> 7;           // warp group 0/1
    const int t128 = tid & 127;
    const int w    = (tid >> 5) & 3;     // warp within group
    const int lid  = tid & 31;
    const int g    = lid >> 2;
    const int t    = lid & 3;
    const int barid = 1 + wg;

    const int pa = blockIdx.x;
    const int b  = blockIdx.y;

#pragma unroll 1
    for (int half = 0; half < 2; half++) {
        const int qb = half ? pa : 31 - pa;
        const int q0 = qb * 64;

        // ---- persistent Q fragments (hi/lo); both groups load same rows ----
        uint32_t qh[8][4], ql[8][4];
        {
            const __nv_bfloat16* qgh = g_qh + ((size_t)b * T + q0 + w * 16) * H;
            const __nv_bfloat16* qgl = g_ql + ((size_t)b * T + q0 + w * 16) * H;
#pragma unroll
            for (int kc = 0; kc < 8; kc++) {
                int cb = kc * 16 + 2 * t;
                qh[kc][0] = *(const uint32_t*)&qgh[(size_t)g       * H + cb];
                qh[kc][1] = *(const uint32_t*)&qgh[(size_t)(g + 8) * H + cb];
                qh[kc][2] = *(const uint32_t*)&qgh[(size_t)g       * H + cb + 8];
                qh[kc][3] = *(const uint32_t*)&qgh[(size_t)(g + 8) * H + cb + 8];
                ql[kc][0] = *(const uint32_t*)&qgl[(size_t)g       * H + cb];
                ql[kc][1] = *(const uint32_t*)&qgl[(size_t)(g + 8) * H + cb];
                ql[kc][2] = *(const uint32_t*)&qgl[(size_t)g       * H + cb + 8];
                ql[kc][3] = *(const uint32_t*)&qgl[(size_t)(g + 8) * H + cb + 8];
            }
        }

        float o[16][4];
#pragma unroll
        for (int nt = 0; nt < 16; nt++)
#pragma unroll
            for (int c = 0; c < 4; c++) o[nt][c] = 0.f;
        float m0 = -1e30f, m1 = -1e30f, l0 = 0.f, l1 = 0.f;

        const int bo = wg * AT_BUF_ELEMS;

        if (wg <= qb) {
            stage_kv(smbase, wg, b, wg * 64, t128);
            CP_COMMIT();
        }

#pragma unroll 1
        for (int kb = wg; kb <= qb; kb += 2) {
            CP_WAIT_ALL();
            BAR_GRP(barid);

            // ---- S = Q K^T, ILP-ordered: blocks of 4 n-tiles ----
            float sC[8][4];
#pragma unroll
            for (int nt = 0; nt < 8; nt++)
#pragma unroll
                for (int c = 0; c < 4; c++) sC[nt][c] = 0.f;

#pragma unroll
            for (int kc = 0; kc < 8; kc++) {
                const int kk = kc * 16 + 2 * t;
#pragma unroll
                for (int nb = 0; nb < 2; nb++) {
                    uint32_t bh[4][2], bl[4][2];
#pragma unroll
                    for (int j = 0; j < 4; j++) {
                        const int n = (nb * 4 + j) * 8 + g;
                        bh[j][0] = *(const uint32_t*)&sm[bo + AT_SKH + n * KSTRIDE + kk];
                        bh[j][1] = *(const uint32_t*)&sm[bo + AT_SKH + n * KSTRIDE + kk + 8];
                        bl[j][0] = *(const uint32_t*)&sm[bo + AT_SKL + n * KSTRIDE + kk];
                        bl[j][1] = *(const uint32_t*)&sm[bo + AT_SKL + n * KSTRIDE + kk + 8];
                    }
#pragma unroll
                    for (int j = 0; j < 4; j++)
                        mma16816(sC[nb * 4 + j], qh[kc], bh[j]);
#pragma unroll
                    for (int j = 0; j < 4; j++)
                        mma16816(sC[nb * 4 + j], qh[kc], bl[j]);
#pragma unroll
                    for (int j = 0; j < 4; j++)
                        mma16816(sC[nb * 4 + j], ql[kc], bh[j]);
                }
            }

            // ---- causal mask (diagonal chunk only) ----
            if (kb == qb) {
                const int rl0 = w * 16 + g;
                const int rl1 = rl0 + 8;
#pragma unroll
                for (int nt = 0; nt < 8; nt++) {
                    int c0 = nt * 8 + 2 * t;
                    if (c0     > rl0) sC[nt][0] = -1e30f;
                    if (c0 + 1 > rl0) sC[nt][1] = -1e30f;
                    if (c0     > rl1) sC[nt][2] = -1e30f;
                    if (c0 + 1 > rl1) sC[nt][3] = -1e30f;
                }
            }

            // ---- online softmax ----
            float mx0 = -1e30f, mx1 = -1e30f;
#pragma unroll
            for (int nt = 0; nt < 8; nt++) {
                mx0 = fmaxf(mx0, fmaxf(sC[nt][0], sC[nt][1]));
                mx1 = fmaxf(mx1, fmaxf(sC[nt][2], sC[nt][3]));
            }
            mx0 = fmaxf(mx0, __shfl_xor_sync(0xffffffffu, mx0, 1));
            mx0 = fmaxf(mx0, __shfl_xor_sync(0xffffffffu, mx0, 2));
            mx1 = fmaxf(mx1, __shfl_xor_sync(0xffffffffu, mx1, 1));
            mx1 = fmaxf(mx1, __shfl_xor_sync(0xffffffffu, mx1, 2));

            float mn0 = fmaxf(m0, mx0), mn1 = fmaxf(m1, mx1);
            float a0 = __expf(m0 - mn0), a1 = __expf(m1 - mn1);
            m0 = mn0; m1 = mn1;

            float rs0 = 0.f, rs1 = 0.f;
#pragma unroll
            for (int nt = 0; nt < 8; nt++) {
                sC[nt][0] = __expf(sC[nt][0] - mn0); rs0 += sC[nt][0];
                sC[nt][1] = __expf(sC[nt][1] - mn0); rs0 += sC[nt][1];
                sC[nt][2] = __expf(sC[nt][2] - mn1); rs1 += sC[nt][2];
                sC[nt][3] = __expf(sC[nt][3] - mn1); rs1 += sC[nt][3];
            }
            rs0 += __shfl_xor_sync(0xffffffffu, rs0, 1);
            rs0 += __shfl_xor_sync(0xffffffffu, rs0, 2);
            rs1 += __shfl_xor_sync(0xffffffffu, rs1, 1);
            rs1 += __shfl_xor_sync(0xffffffffu, rs1, 2);
            l0 = l0 * a0 + rs0;
            l1 = l1 * a1 + rs1;

#pragma unroll
            for (int nt = 0; nt < 16; nt++) {
                o[nt][0] *= a0; o[nt][1] *= a0;
                o[nt][2] *= a1; o[nt][3] *= a1;
            }

            // ---- pack P C-frags -> A-frags (hi/lo) ----
            uint32_t pah[4][4], pal[4][4];
#pragma unroll
            for (int kc = 0; kc < 4; kc++) {
                pah[kc][0] = pack_split(sC[2 * kc][0],     sC[2 * kc][1],     pal[kc][0]);
                pah[kc][1] = pack_split(sC[2 * kc][2],     sC[2 * kc][3],     pal[kc][1]);
                pah[kc][2] = pack_split(sC[2 * kc + 1][0], sC[2 * kc + 1][1], pal[kc][2]);
                pah[kc][3] = pack_split(sC[2 * kc + 1][2], sC[2 * kc + 1][3], pal[kc][3]);
            }

            // ---- O += P V, ILP-ordered: blocks of 4 n-tiles ----
#pragma unroll
            for (int kc = 0; kc < 4; kc++) {
                const int kk = kc * 16 + 2 * t;
#pragma unroll
                for (int nb = 0; nb < 4; nb++) {
                    uint32_t vh[4][2], vl[4][2];
#pragma unroll
                    for (int j = 0; j < 4; j++) {
                        const int n = (nb * 4 + j) * 8 + g;
                        vh[j][0] = *(const uint32_t*)&sm[bo + AT_SVH + n * VSTRIDE + kk];
                        vh[j][1] = *(const uint32_t*)&sm[bo + AT_SVH + n * VSTRIDE + kk + 8];
                        vl[j][0] = *(const uint32_t*)&sm[bo + AT_SVL + n * VSTRIDE + kk];
                        vl[j][1] = *(const uint32_t*)&sm[bo + AT_SVL + n * VSTRIDE + kk + 8];
                    }
#pragma unroll
                    for (int j = 0; j < 4; j++)
                        mma16816(o[nb * 4 + j], pah[kc], vh[j]);
#pragma unroll
                    for (int j = 0; j < 4; j++)
                        mma16816(o[nb * 4 + j], pah[kc], vl[j]);
#pragma unroll
                    for (int j = 0; j < 4; j++)
                        mma16816(o[nb * 4 + j], pal[kc], vh[j]);
                }
            }

            BAR_GRP(barid);   // group done reading buffer
            if (kb + 2 <= qb) {
                stage_kv(smbase, wg, b, (kb + 2) * 64, t128);
                CP_COMMIT();
            }
        }

        // ---- merge the two groups' states ----
        __syncthreads();                         // all KV traffic done
        float* ms = (float*)att_sm;              // aliases KV buffers
        if (wg == 1) {
            const int base = t128 * MSTRIDE;
#pragma unroll
            for (int nt = 0; nt < 16; nt++)
#pragma unroll
                for (int c = 0; c < 4; c++)
                    ms[base + nt * 4 + c] = o[nt][c];
            ms[base + 64] = m0;
            ms[base + 65] = l0;
            ms[base + 66] = m1;
            ms[base + 67] = l1;
        }
        __syncthreads();
        if (wg == 0) {
            const int base = t128 * MSTRIDE;
            float sm0 = ms[base + 64], sl0 = ms[base + 65];
            float sm1 = ms[base + 66], sl1 = ms[base + 67];
            float M0 = fmaxf(m0, sm0), M1 = fmaxf(m1, sm1);
            float a0 = __expf(m0 - M0), b0 = __expf(sm0 - M0);
            float a1 = __expf(m1 - M1), b1 = __expf(sm1 - M1);
            float inv0 = 1.0f / (l0 * a0 + sl0 * b0);
            float inv1 = 1.0f / (l1 * a1 + sl1 * b1);

            float* og = out + ((size_t)b * T + q0 + w * 16) * H;
#pragma unroll
            for (int nt = 0; nt < 16; nt++) {
                int c = nt * 8 + 2 * t;
                float r00 = (o[nt][0] * a0 + ms[base + nt * 4 + 0] * b0) * inv0;
                float r01 = (o[nt][1] * a0 + ms[base + nt * 4 + 1] * b0) * inv0;
                float r10 = (o[nt][2] * a1 + ms[base + nt * 4 + 2] * b1) * inv1;
                float r11 = (o[nt][3] * a1 + ms[base + nt * 4 + 3] * b1) * inv1;
                *(float2*)&og[(size_t)g * H + c]       = make_float2(r00, r01);
                *(float2*)&og[(size_t)(g + 8) * H + c] = make_float2(r10, r11);
            }
        }
        __syncthreads();                         // merge reads done
    }
}

// ---------------------------------------------------------------------------
extern "C" void kernel_launch(void* const* d_in, const int* in_sizes, int n_in,
                              void* d_out, int out_size)
{
    (void)in_sizes; (void)n_in; (void)out_size;
    const float* x  = (const float*)d_in[0];
    const float* Wq = (const float*)d_in[1];
    const float* Wk = (const float*)d_in[2];
    const float* Wv = (const float*)d_in[3];
    float* out = (float*)d_out;

    split_x_kernel<<<BT * NE / 4 / 1024, 256>>>(x);

    dim3 gw(512, 3);
    split_w_kernel<<<gw, 256>>>(Wq, Wk, Wv);

    cudaFuncSetAttribute(qkv_mma_kernel,
                         cudaFuncAttributeMaxDynamicSharedMemorySize, GEMM_SMEM_BYTES);
    dim3 g1(BT / GM_TILE, 3);
    qkv_mma_kernel<<<g1, GTHREADS, GEMM_SMEM_BYTES>>>();

    cudaFuncSetAttribute(attn_mma_kernel,
                         cudaFuncAttributeMaxDynamicSharedMemorySize, AT_SMEM_BYTES);
    dim3 g2(16, NB);
    attn_mma_kernel<<<g2, 256, AT_SMEM_BYTES>>>(out);
}

// round 16
// speedup vs baseline: 1.1185x; 1.1185x over previous
#include <cuda_runtime.h>
#include <cuda_bf16.h>
#include <math.h>
#include <stdint.h>

// Problem constants
#define NB   8
#define T    2048
#define NE   1024
#define H    128
#define BT   (NB * T)   // 16384

// ---------------------------------------------------------------------------
// Device-global scratch (no allocs allowed)
// ---------------------------------------------------------------------------
__device__ __nv_bfloat16 g_qh[BT * H];             // q hi (pre-scaled 1/32)
__device__ __nv_bfloat16 g_ql[BT * H];             // q lo
__device__ __nv_bfloat16 g_kh[BT * H];             // k hi
__device__ __nv_bfloat16 g_kl[BT * H];             // k lo
__device__ __nv_bfloat16 g_vth[NB * H * T];        // v^T hi: [b][h][t]
__device__ __nv_bfloat16 g_vtl[NB * H * T];        // v^T lo

__device__ __nv_bfloat16 g_xh[BT * NE];            // x hi split
__device__ __nv_bfloat16 g_xl[BT * NE];            // x lo split
__device__ __nv_bfloat16 g_wth[3 * H * NE];        // W^T hi: [mat][n][k]
__device__ __nv_bfloat16 g_wtl[3 * H * NE];        // W^T lo

// ---------------------------------------------------------------------------
// PTX helpers
// ---------------------------------------------------------------------------
__device__ __forceinline__ void mma16816(float* d,
                                         const uint32_t* a,
                                         const uint32_t* b)
{
    asm volatile(
        "mma.sync.aligned.m16n8k16.row.col.f32.bf16.bf16.f32 "
        "{%0,%1,%2,%3}, {%4,%5,%6,%7}, {%8,%9}, {%0,%1,%2,%3};"
        : "+f"(d[0]), "+f"(d[1]), "+f"(d[2]), "+f"(d[3])
        : "r"(a[0]), "r"(a[1]), "r"(a[2]), "r"(a[3]),
          "r"(b[0]), "r"(b[1]));
}

__device__ __forceinline__ uint32_t smem_u32(const void* p) {
    return (uint32_t)__cvta_generic_to_shared(p);
}

__device__ __forceinline__ void cp16(uint32_t saddr, const void* gptr) {
    asm volatile("cp.async.cg.shared.global [%0], [%1], 16;"
                 :: "r"(saddr), "l"(__cvta_generic_to_global(gptr)) : "memory");
}

#define CP_COMMIT()   asm volatile("cp.async.commit_group;" ::: "memory")
#define CP_WAIT_ALL() asm volatile("cp.async.wait_group 0;" ::: "memory")
#define CP_WAIT_1()   asm volatile("cp.async.wait_group 1;" ::: "memory")
#define BAR_GRP(id)   asm volatile("bar.sync %0, 128;" :: "r"(id) : "memory")

// split a float pair into packed bf16x2 hi and lo
__device__ __forceinline__ uint32_t pack_split(float x, float y, uint32_t& lo)
{
    __nv_bfloat16 hx = __float2bfloat16_rn(x);
    __nv_bfloat16 hy = __float2bfloat16_rn(y);
    __nv_bfloat162 hp(hx, hy);
    __nv_bfloat162 lp(__float2bfloat16_rn(x - __bfloat162float(hx)),
                      __float2bfloat16_rn(y - __bfloat162float(hy)));
    lo = *(uint32_t*)&lp;
    return *(uint32_t*)&hp;
}

// ---------------------------------------------------------------------------
// Prep: split x into bf16 hi/lo — 4x MLP version
// ---------------------------------------------------------------------------
__global__ __launch_bounds__(256)
void split_x_kernel(const float* __restrict__ x)
{
    const int base = blockIdx.x * 1024 + threadIdx.x;   // float4 index
    float4 v[4];
#pragma unroll
    for (int j = 0; j < 4; j++)
        v[j] = ((const float4*)x)[base + j * 256];

    __nv_bfloat162* ph = (__nv_bfloat162*)g_xh;
    __nv_bfloat162* pl = (__nv_bfloat162*)g_xl;
#pragma unroll
    for (int j = 0; j < 4; j++) {
        const int i = base + j * 256;
        __nv_bfloat16 h0 = __float2bfloat16_rn(v[j].x);
        __nv_bfloat16 h1 = __float2bfloat16_rn(v[j].y);
        __nv_bfloat16 h2 = __float2bfloat16_rn(v[j].z);
        __nv_bfloat16 h3 = __float2bfloat16_rn(v[j].w);
        __nv_bfloat16 l0 = __float2bfloat16_rn(v[j].x - __bfloat162float(h0));
        __nv_bfloat16 l1 = __float2bfloat16_rn(v[j].y - __bfloat162float(h1));
        __nv_bfloat16 l2 = __float2bfloat16_rn(v[j].z - __bfloat162float(h2));
        __nv_bfloat16 l3 = __float2bfloat16_rn(v[j].w - __bfloat162float(h3));
        ph[2 * i]     = __nv_bfloat162(h0, h1);
        ph[2 * i + 1] = __nv_bfloat162(h2, h3);
        pl[2 * i]     = __nv_bfloat162(l0, l1);
        pl[2 * i + 1] = __nv_bfloat162(l2, l3);
    }
}

// ---------------------------------------------------------------------------
// Prep: transpose + split W (3 matrices) -> [mat][n][k] bf16 hi/lo
// ---------------------------------------------------------------------------
__global__ __launch_bounds__(256)
void split_w_kernel(const float* __restrict__ Wq,
                    const float* __restrict__ Wk,
                    const float* __restrict__ Wv)
{
    int mat = blockIdx.y;
    const float* W = (mat == 0) ? Wq : (mat == 1) ? Wk : Wv;
    int i = blockIdx.x * 256 + threadIdx.x;
    int k = i >> 7;
    int n = i & 127;
    float w = W[i];
    __nv_bfloat16 hi = __float2bfloat16_rn(w);
    __nv_bfloat16 lo = __float2bfloat16_rn(w - __bfloat162float(hi));
    size_t o = (size_t)mat * (H * NE) + (size_t)n * NE + k;
    g_wth[o] = hi;
    g_wtl[o] = lo;
}

// ---------------------------------------------------------------------------
// QKV GEMM via mma.sync (bf16 hi/lo split, fp32 accum),
// cp.async DOUBLE-BUFFERED staging, ILP-ordered MMAs (R13 form, verbatim).
// mat==2 epilogue: in-kernel transpose+split of v -> g_vth/g_vtl.
// ---------------------------------------------------------------------------
#define KC      64
#define TSTRIDE 72
#define TILE_BF (128 * TSTRIDE)
#define GBUF_ELEMS (4 * TILE_BF)                 // one buffer: xh,xl,wh,wl
#define GEMM_SMEM_BYTES (2 * GBUF_ELEMS * 2)     // 147456

extern __shared__ __nv_bfloat16 gsm[];

__device__ __forceinline__ void gemm_stage(uint32_t sb, int buf, int m0,
                                           const __nv_bfloat16* wh_base,
                                           const __nv_bfloat16* wl_base,
                                           int k0, int tid)
{
    const uint32_t base = sb + buf * (GBUF_ELEMS * 2);
#pragma unroll
    for (int it = 0; it < 4; it++) {
        int idx = it * 256 + tid;
        int r  = idx >> 3;
        int c8 = (idx & 7) * 8;
        size_t xs = (size_t)(m0 + r) * NE + k0 + c8;
        size_t ws = (size_t)r * NE + k0 + c8;
        uint32_t dsto = (r * TSTRIDE + c8) * 2;
        cp16(base + 0 * TILE_BF * 2 + dsto, g_xh + xs);
        cp16(base + 1 * TILE_BF * 2 + dsto, g_xl + xs);
        cp16(base + 2 * TILE_BF * 2 + dsto, wh_base + ws);
        cp16(base + 3 * TILE_BF * 2 + dsto, wl_base + ws);
    }
}

__global__ __launch_bounds__(256)
void qkv_mma_kernel()
{
    const uint32_t sb = smem_u32(gsm);

    const int tid = threadIdx.x;
    const int wid = tid >> 5;
    const int lid = tid & 31;
    const int g   = lid >> 2;
    const int t   = lid & 3;

    const int m0  = blockIdx.x * 128;
    const int mat = blockIdx.y;
    const int wm  = (wid >> 1) * 32;
    const int wn  = (wid & 1) * 64;

    const __nv_bfloat16* wh_base = g_wth + (size_t)mat * (H * NE);
    const __nv_bfloat16* wl_base = g_wtl + (size_t)mat * (H * NE);

    float acc[2][8][4];
#pragma unroll
    for (int mi = 0; mi < 2; mi++)
#pragma unroll
        for (int ni = 0; ni < 8; ni++)
#pragma unroll
            for (int c = 0; c < 4; c++) acc[mi][ni][c] = 0.f;

    gemm_stage(sb, 0, m0, wh_base, wl_base, 0, tid);
    CP_COMMIT();

    for (int kc = 0; kc < 16; kc++) {
        if (kc < 15) {
            gemm_stage(sb, (kc + 1) & 1, m0, wh_base, wl_base, (kc + 1) * KC, tid);
            CP_COMMIT();
            CP_WAIT_1();
        } else {
            CP_WAIT_ALL();
        }
        __syncthreads();

        const __nv_bfloat16* Axh = gsm + (kc & 1) * GBUF_ELEMS;
        const __nv_bfloat16* Axl = Axh + TILE_BF;
        const __nv_bfloat16* Bwh = Axl + TILE_BF;
        const __nv_bfloat16* Bwl = Bwh + TILE_BF;

#pragma unroll
        for (int ks = 0; ks < 4; ks++) {
            const int kk = ks * 16;
            uint32_t ah[2][4], al[2][4];
#pragma unroll
            for (int mi = 0; mi < 2; mi++) {
                int r = wm + mi * 16;
                ah[mi][0] = *(const uint32_t*)&Axh[(r + g    ) * TSTRIDE + kk + 2 * t    ];
                ah[mi][1] = *(const uint32_t*)&Axh[(r + g + 8) * TSTRIDE + kk + 2 * t    ];
                ah[mi][2] = *(const uint32_t*)&Axh[(r + g    ) * TSTRIDE + kk + 2 * t + 8];
                ah[mi][3] = *(const uint32_t*)&Axh[(r + g + 8) * TSTRIDE + kk + 2 * t + 8];
                al[mi][0] = *(const uint32_t*)&Axl[(r + g    ) * TSTRIDE + kk + 2 * t    ];
                al[mi][1] = *(const uint32_t*)&Axl[(r + g + 8) * TSTRIDE + kk + 2 * t    ];
                al[mi][2] = *(const uint32_t*)&Axl[(r + g    ) * TSTRIDE + kk + 2 * t + 8];
                al[mi][3] = *(const uint32_t*)&Axl[(r + g + 8) * TSTRIDE + kk + 2 * t + 8];
            }
            // block-of-4 n-tiles: 8 independent MMAs between accumulator reuse
#pragma unroll
            for (int nb = 0; nb < 2; nb++) {
                uint32_t bh[4][2], bl[4][2];
#pragma unroll
                for (int j = 0; j < 4; j++) {
                    int nr = wn + (nb * 4 + j) * 8 + g;
                    bh[j][0] = *(const uint32_t*)&Bwh[nr * TSTRIDE + kk + 2 * t    ];
                    bh[j][1] = *(const uint32_t*)&Bwh[nr * TSTRIDE + kk + 2 * t + 8];
                    bl[j][0] = *(const uint32_t*)&Bwl[nr * TSTRIDE + kk + 2 * t    ];
                    bl[j][1] = *(const uint32_t*)&Bwl[nr * TSTRIDE + kk + 2 * t + 8];
                }
#pragma unroll
                for (int j = 0; j < 4; j++)
#pragma unroll
                    for (int mi = 0; mi < 2; mi++)
                        mma16816(acc[mi][nb * 4 + j], ah[mi], bh[j]);
#pragma unroll
                for (int j = 0; j < 4; j++)
#pragma unroll
                    for (int mi = 0; mi < 2; mi++)
                        mma16816(acc[mi][nb * 4 + j], ah[mi], bl[j]);
#pragma unroll
                for (int j = 0; j < 4; j++)
#pragma unroll
                    for (int mi = 0; mi < 2; mi++)
                        mma16816(acc[mi][nb * 4 + j], al[mi], bh[j]);
            }
        }
        __syncthreads();
    }

    // epilogue
    if (mat == 2) {
        // stage v tile (fp32) to smem, then transposed+split write to g_vt*
        float* ep = (float*)gsm;                 // 128 x 132 fp32 = 66 KB
#pragma unroll
        for (int mi = 0; mi < 2; mi++)
#pragma unroll
            for (int ni = 0; ni < 8; ni++) {
                int lr = wm + mi * 16 + g;
                int c  = wn + ni * 8 + 2 * t;
                ep[lr * 132 + c]           = acc[mi][ni][0];
                ep[lr * 132 + c + 1]       = acc[mi][ni][1];
                ep[(lr + 8) * 132 + c]     = acc[mi][ni][2];
                ep[(lr + 8) * 132 + c + 1] = acc[mi][ni][3];
            }
        __syncthreads();

        const int b  = m0 >> 11;                 // batch
        const int t0 = m0 & 2047;                // t offset within batch
        const int h   = tid & 127;
        const int sel = tid >> 7;                // 0 = hi, 1 = lo
        __nv_bfloat16* dst = sel ? g_vtl : g_vth;
        __nv_bfloat16* drow = dst + ((size_t)b * H + h) * T + t0;
#pragma unroll
        for (int j8 = 0; j8 < 16; j8++) {
            union { __nv_bfloat16 bh[8]; uint4 u4; } tmp;
#pragma unroll
            for (int u = 0; u < 8; u++) {
                float v = ep[(j8 * 8 + u) * 132 + h];
                __nv_bfloat16 hi = __float2bfloat16_rn(v);
                tmp.bh[u] = sel ? __float2bfloat16_rn(v - __bfloat162float(hi))
                                : hi;
            }
            *(uint4*)&drow[j8 * 8] = tmp.u4;
        }
    } else {
        const float sc = (mat == 0) ? 0.03125f : 1.0f;
        __nv_bfloat16* dh = (mat == 0) ? g_qh : g_kh;
        __nv_bfloat16* dl = (mat == 0) ? g_ql : g_kl;
#pragma unroll
        for (int mi = 0; mi < 2; mi++)
#pragma unroll
            for (int ni = 0; ni < 8; ni++) {
                int r0 = m0 + wm + mi * 16 + g;
                int c  = wn + ni * 8 + 2 * t;
                uint32_t lo0, lo1;
                uint32_t hi0 = pack_split(acc[mi][ni][0] * sc, acc[mi][ni][1] * sc, lo0);
                uint32_t hi1 = pack_split(acc[mi][ni][2] * sc, acc[mi][ni][3] * sc, lo1);
                *(uint32_t*)&dh[(size_t)r0 * H + c]       = hi0;
                *(uint32_t*)&dl[(size_t)r0 * H + c]       = lo0;
                *(uint32_t*)&dh[(size_t)(r0 + 8) * H + c] = hi1;
                *(uint32_t*)&dl[(size_t)(r0 + 8) * H + c] = lo1;
            }
    }
}

// ---------------------------------------------------------------------------
// Flash attention: split-K across 2 warp groups (256 threads), plain-LDS
// frag loads, ILP-ordered MMAs. K and V staged in SEPARATE commit groups:
// the V wait hides under S+softmax and the K(kb+2) prefetch hides under PV.
// Group wg handles kv-chunks kb ≡ wg (mod 2) in its own buffer; states
// merged at the end. Grid (16, 8), paired q-tiles.
// ---------------------------------------------------------------------------
#define KSTRIDE 136
#define VSTRIDE 72
#define AT_SKH  0
#define AT_SKL  (64 * KSTRIDE)
#define AT_SVH  (2 * 64 * KSTRIDE)
#define AT_SVL  (2 * 64 * KSTRIDE + 128 * VSTRIDE)
#define AT_BUF_ELEMS (2 * 64 * KSTRIDE + 2 * 128 * VSTRIDE)   // 35840
#define AT_SMEM_BYTES (2 * AT_BUF_ELEMS * 2)                  // 143360
#define MSTRIDE 69                                            // merge stride

extern __shared__ __nv_bfloat16 att_sm[];

__device__ __forceinline__ void stage_k(uint32_t smbase, int buf, int b,
                                        int kv0, int t128)
{
    const __nv_bfloat16* kh = g_kh + ((size_t)b * T + kv0) * H;
    const __nv_bfloat16* kl = g_kl + ((size_t)b * T + kv0) * H;
    const uint32_t base = smbase + buf * (AT_BUF_ELEMS * 2);
#pragma unroll
    for (int it = 0; it < 8; it++) {
        int idx = it * 128 + t128;
        int r  = idx >> 4;
        int c8 = (idx & 15) * 8;
        cp16(base + (AT_SKH + r * KSTRIDE + c8) * 2, kh + (size_t)r * H + c8);
        cp16(base + (AT_SKL + r * KSTRIDE + c8) * 2, kl + (size_t)r * H + c8);
    }
}

__device__ __forceinline__ void stage_v(uint32_t smbase, int buf, int b,
                                        int kv0, int t128)
{
    const __nv_bfloat16* vth = g_vth + (size_t)b * H * T + kv0;
    const __nv_bfloat16* vtl = g_vtl + (size_t)b * H * T + kv0;
    const uint32_t base = smbase + buf * (AT_BUF_ELEMS * 2);
#pragma unroll
    for (int it = 0; it < 8; it++) {
        int idx = it * 128 + t128;
        int r  = idx >> 3;
        int c8 = (idx & 7) * 8;
        cp16(base + (AT_SVH + r * VSTRIDE + c8) * 2, vth + (size_t)r * T + c8);
        cp16(base + (AT_SVL + r * VSTRIDE + c8) * 2, vtl + (size_t)r * T + c8);
    }
}

__global__ __launch_bounds__(256, 1)
void attn_mma_kernel(float* __restrict__ out)
{
    __nv_bfloat16* sm = att_sm;
    const uint32_t smbase = smem_u32(att_sm);
    const int tid  = threadIdx.x;
    const int wg   = tid >> 7;           // warp group 0/1
    const int t128 = tid & 127;
    const int w    = (tid >> 5) & 3;     // warp within group
    const int lid  = tid & 31;
    const int g    = lid >> 2;
    const int t    = lid & 3;
    const int barid = 1 + wg;

    const int pa = blockIdx.x;
    const int b  = blockIdx.y;

#pragma unroll 1
    for (int half = 0; half < 2; half++) {
        const int qb = half ? pa : 31 - pa;
        const int q0 = qb * 64;

        // ---- persistent Q fragments (hi/lo); both groups load same rows ----
        uint32_t qh[8][4], ql[8][4];
        {
            const __nv_bfloat16* qgh = g_qh + ((size_t)b * T + q0 + w * 16) * H;
            const __nv_bfloat16* qgl = g_ql + ((size_t)b * T + q0 + w * 16) * H;
#pragma unroll
            for (int kc = 0; kc < 8; kc++) {
                int cb = kc * 16 + 2 * t;
                qh[kc][0] = *(const uint32_t*)&qgh[(size_t)g       * H + cb];
                qh[kc][1] = *(const uint32_t*)&qgh[(size_t)(g + 8) * H + cb];
                qh[kc][2] = *(const uint32_t*)&qgh[(size_t)g       * H + cb + 8];
                qh[kc][3] = *(const uint32_t*)&qgh[(size_t)(g + 8) * H + cb + 8];
                ql[kc][0] = *(const uint32_t*)&qgl[(size_t)g       * H + cb];
                ql[kc][1] = *(const uint32_t*)&qgl[(size_t)(g + 8) * H + cb];
                ql[kc][2] = *(const uint32_t*)&qgl[(size_t)g       * H + cb + 8];
                ql[kc][3] = *(const uint32_t*)&qgl[(size_t)(g + 8) * H + cb + 8];
            }
        }

        float o[16][4];
#pragma unroll
        for (int nt = 0; nt < 16; nt++)
#pragma unroll
            for (int c = 0; c < 4; c++) o[nt][c] = 0.f;
        float m0 = -1e30f, m1 = -1e30f, l0 = 0.f, l1 = 0.f;

        const int bo = wg * AT_BUF_ELEMS;

        if (wg <= qb) {
            stage_k(smbase, wg, b, wg * 64, t128);
            CP_COMMIT();
            stage_v(smbase, wg, b, wg * 64, t128);
            CP_COMMIT();
        }

#pragma unroll 1
        for (int kb = wg; kb <= qb; kb += 2) {
            CP_WAIT_1();          // K(kb) arrived (V may still be in flight)
            BAR_GRP(barid);       // K visible to all group warps

            // ---- S = Q K^T, ILP-ordered: blocks of 4 n-tiles ----
            float sC[8][4];
#pragma unroll
            for (int nt = 0; nt < 8; nt++)
#pragma unroll
                for (int c = 0; c < 4; c++) sC[nt][c] = 0.f;

#pragma unroll
            for (int kc = 0; kc < 8; kc++) {
                const int kk = kc * 16 + 2 * t;
#pragma unroll
                for (int nb = 0; nb < 2; nb++) {
                    uint32_t bh[4][2], bl[4][2];
#pragma unroll
                    for (int j = 0; j < 4; j++) {
                        const int n = (nb * 4 + j) * 8 + g;
                        bh[j][0] = *(const uint32_t*)&sm[bo + AT_SKH + n * KSTRIDE + kk];
                        bh[j][1] = *(const uint32_t*)&sm[bo + AT_SKH + n * KSTRIDE + kk + 8];
                        bl[j][0] = *(const uint32_t*)&sm[bo + AT_SKL + n * KSTRIDE + kk];
                        bl[j][1] = *(const uint32_t*)&sm[bo + AT_SKL + n * KSTRIDE + kk + 8];
                    }
#pragma unroll
                    for (int j = 0; j < 4; j++)
                        mma16816(sC[nb * 4 + j], qh[kc], bh[j]);
#pragma unroll
                    for (int j = 0; j < 4; j++)
                        mma16816(sC[nb * 4 + j], qh[kc], bl[j]);
#pragma unroll
                    for (int j = 0; j < 4; j++)
                        mma16816(sC[nb * 4 + j], ql[kc], bh[j]);
                }
            }

            // ---- causal mask (diagonal chunk only) ----
            if (kb == qb) {
                const int rl0 = w * 16 + g;
                const int rl1 = rl0 + 8;
#pragma unroll
                for (int nt = 0; nt < 8; nt++) {
                    int c0 = nt * 8 + 2 * t;
                    if (c0     > rl0) sC[nt][0] = -1e30f;
                    if (c0 + 1 > rl0) sC[nt][1] = -1e30f;
                    if (c0     > rl1) sC[nt][2] = -1e30f;
                    if (c0 + 1 > rl1) sC[nt][3] = -1e30f;
                }
            }

            // ---- online softmax ----
            float mx0 = -1e30f, mx1 = -1e30f;
#pragma unroll
            for (int nt = 0; nt < 8; nt++) {
                mx0 = fmaxf(mx0, fmaxf(sC[nt][0], sC[nt][1]));
                mx1 = fmaxf(mx1, fmaxf(sC[nt][2], sC[nt][3]));
            }
            mx0 = fmaxf(mx0, __shfl_xor_sync(0xffffffffu, mx0, 1));
            mx0 = fmaxf(mx0, __shfl_xor_sync(0xffffffffu, mx0, 2));
            mx1 = fmaxf(mx1, __shfl_xor_sync(0xffffffffu, mx1, 1));
            mx1 = fmaxf(mx1, __shfl_xor_sync(0xffffffffu, mx1, 2));

            float mn0 = fmaxf(m0, mx0), mn1 = fmaxf(m1, mx1);
            float a0 = __expf(m0 - mn0), a1 = __expf(m1 - mn1);
            m0 = mn0; m1 = mn1;

            float rs0 = 0.f, rs1 = 0.f;
#pragma unroll
            for (int nt = 0; nt < 8; nt++) {
                sC[nt][0] = __expf(sC[nt][0] - mn0); rs0 += sC[nt][0];
                sC[nt][1] = __expf(sC[nt][1] - mn0); rs0 += sC[nt][1];
                sC[nt][2] = __expf(sC[nt][2] - mn1); rs1 += sC[nt][2];
                sC[nt][3] = __expf(sC[nt][3] - mn1); rs1 += sC[nt][3];
            }
            rs0 += __shfl_xor_sync(0xffffffffu, rs0, 1);
            rs0 += __shfl_xor_sync(0xffffffffu, rs0, 2);
            rs1 += __shfl_xor_sync(0xffffffffu, rs1, 1);
            rs1 += __shfl_xor_sync(0xffffffffu, rs1, 2);
            l0 = l0 * a0 + rs0;
            l1 = l1 * a1 + rs1;

#pragma unroll
            for (int nt = 0; nt < 16; nt++) {
                o[nt][0] *= a0; o[nt][1] *= a0;
                o[nt][2] *= a1; o[nt][3] *= a1;
            }

            // ---- pack P C-frags -> A-frags (hi/lo) ----
            uint32_t pah[4][4], pal[4][4];
#pragma unroll
            for (int kc = 0; kc < 4; kc++) {
                pah[kc][0] = pack_split(sC[2 * kc][0],     sC[2 * kc][1],     pal[kc][0]);
                pah[kc][1] = pack_split(sC[2 * kc][2],     sC[2 * kc][3],     pal[kc][1]);
                pah[kc][2] = pack_split(sC[2 * kc + 1][0], sC[2 * kc + 1][1], pal[kc][2]);
                pah[kc][3] = pack_split(sC[2 * kc + 1][2], sC[2 * kc + 1][3], pal[kc][3]);
            }

            BAR_GRP(barid);       // all group warps done reading K buffer
            if (kb + 2 <= qb) {
                stage_k(smbase, wg, b, (kb + 2) * 64, t128);
                CP_COMMIT();
                CP_WAIT_1();      // V(kb) arrived (K(kb+2) still in flight)
            } else {
                CP_WAIT_ALL();    // V(kb) arrived
            }
            BAR_GRP(barid);       // V visible to all group warps

            // ---- O += P V, ILP-ordered: blocks of 4 n-tiles ----
#pragma unroll
            for (int kc = 0; kc < 4; kc++) {
                const int kk = kc * 16 + 2 * t;
#pragma unroll
                for (int nb = 0; nb < 4; nb++) {
                    uint32_t vh[4][2], vl[4][2];
#pragma unroll
                    for (int j = 0; j < 4; j++) {
                        const int n = (nb * 4 + j) * 8 + g;
                        vh[j][0] = *(const uint32_t*)&sm[bo + AT_SVH + n * VSTRIDE + kk];
                        vh[j][1] = *(const uint32_t*)&sm[bo + AT_SVH + n * VSTRIDE + kk + 8];
                        vl[j][0] = *(const uint32_t*)&sm[bo + AT_SVL + n * VSTRIDE + kk];
                        vl[j][1] = *(const uint32_t*)&sm[bo + AT_SVL + n * VSTRIDE + kk + 8];
                    }
#pragma unroll
                    for (int j = 0; j < 4; j++)
                        mma16816(o[nb * 4 + j], pah[kc], vh[j]);
#pragma unroll
                    for (int j = 0; j < 4; j++)
                        mma16816(o[nb * 4 + j], pah[kc], vl[j]);
#pragma unroll
                    for (int j = 0; j < 4; j++)
                        mma16816(o[nb * 4 + j], pal[kc], vh[j]);
                }
            }

            BAR_GRP(barid);       // all group warps done reading V buffer
            if (kb + 2 <= qb) {
                stage_v(smbase, wg, b, (kb + 2) * 64, t128);
                CP_COMMIT();
            }
        }

        // ---- merge the two groups' states ----
        __syncthreads();                         // all KV traffic done
        float* ms = (float*)att_sm;              // aliases KV buffers
        if (wg == 1) {
            const int base = t128 * MSTRIDE;
#pragma unroll
            for (int nt = 0; nt < 16; nt++)
#pragma unroll
                for (int c = 0; c < 4; c++)
                    ms[base + nt * 4 + c] = o[nt][c];
            ms[base + 64] = m0;
            ms[base + 65] = l0;
            ms[base + 66] = m1;
            ms[base + 67] = l1;
        }
        __syncthreads();
        if (wg == 0) {
            const int base = t128 * MSTRIDE;
            float sm0 = ms[base + 64], sl0 = ms[base + 65];
            float sm1 = ms[base + 66], sl1 = ms[base + 67];
            float M0 = fmaxf(m0, sm0), M1 = fmaxf(m1, sm1);
            float a0 = __expf(m0 - M0), b0 = __expf(sm0 - M0);
            float a1 = __expf(m1 - M1), b1 = __expf(sm1 - M1);
            float inv0 = 1.0f / (l0 * a0 + sl0 * b0);
            float inv1 = 1.0f / (l1 * a1 + sl1 * b1);

            float* og = out + ((size_t)b * T + q0 + w * 16) * H;
#pragma unroll
            for (int nt = 0; nt < 16; nt++) {
                int c = nt * 8 + 2 * t;
                float r00 = (o[nt][0] * a0 + ms[base + nt * 4 + 0] * b0) * inv0;
                float r01 = (o[nt][1] * a0 + ms[base + nt * 4 + 1] * b0) * inv0;
                float r10 = (o[nt][2] * a1 + ms[base + nt * 4 + 2] * b1) * inv1;
                float r11 = (o[nt][3] * a1 + ms[base + nt * 4 + 3] * b1) * inv1;
                *(float2*)&og[(size_t)g * H + c]       = make_float2(r00, r01);
                *(float2*)&og[(size_t)(g + 8) * H + c] = make_float2(r10, r11);
            }
        }
        __syncthreads();                         // merge reads done
    }
}

// ---------------------------------------------------------------------------
extern "C" void kernel_launch(void* const* d_in, const int* in_sizes, int n_in,
                              void* d_out, int out_size)
{
    (void)in_sizes; (void)n_in; (void)out_size;
    const float* x  = (const float*)d_in[0];
    const float* Wq = (const float*)d_in[1];
    const float* Wk = (const float*)d_in[2];
    const float* Wv = (const float*)d_in[3];
    float* out = (float*)d_out;

    split_x_kernel<<<BT * NE / 4 / 1024, 256>>>(x);

    dim3 gw(512, 3);
    split_w_kernel<<<gw, 256>>>(Wq, Wk, Wv);

    cudaFuncSetAttribute(qkv_mma_kernel,
                         cudaFuncAttributeMaxDynamicSharedMemorySize, GEMM_SMEM_BYTES);
    dim3 g1(BT / 128, 3);
    qkv_mma_kernel<<<g1, 256, GEMM_SMEM_BYTES>>>();

    cudaFuncSetAttribute(attn_mma_kernel,
                         cudaFuncAttributeMaxDynamicSharedMemorySize, AT_SMEM_BYTES);
    dim3 g2(16, NB);
    attn_mma_kernel<<<g2, 256, AT_SMEM_BYTES>>>(out);
}

// round 17
// speedup vs baseline: 1.1707x; 1.0467x over previous
#include <cuda_runtime.h>
#include <cuda_bf16.h>
#include <math.h>
#include <stdint.h>

// Problem constants
#define NB   8
#define T    2048
#define NE   1024
#define H    128
#define BT   (NB * T)   // 16384

// ---------------------------------------------------------------------------
// Device-global scratch (no allocs allowed)
// ---------------------------------------------------------------------------
__device__ __nv_bfloat16 g_qh[BT * H];             // q hi (pre-scaled 1/32)
__device__ __nv_bfloat16 g_ql[BT * H];             // q lo
__device__ __nv_bfloat16 g_kh[BT * H];             // k hi
__device__ __nv_bfloat16 g_kl[BT * H];             // k lo
__device__ __nv_bfloat16 g_vth[NB * H * T];        // v^T hi: [b][h][t]
__device__ __nv_bfloat16 g_vtl[NB * H * T];        // v^T lo

__device__ __nv_bfloat16 g_xh[BT * NE];            // x hi split
__device__ __nv_bfloat16 g_xl[BT * NE];            // x lo split
__device__ __nv_bfloat16 g_wth[3 * H * NE];        // W^T hi: [mat][n][k]
__device__ __nv_bfloat16 g_wtl[3 * H * NE];        // W^T lo

// ---------------------------------------------------------------------------
// PTX helpers
// ---------------------------------------------------------------------------
__device__ __forceinline__ void mma16816(float* d,
                                         const uint32_t* a,
                                         const uint32_t* b)
{
    asm volatile(
        "mma.sync.aligned.m16n8k16.row.col.f32.bf16.bf16.f32 "
        "{%0,%1,%2,%3}, {%4,%5,%6,%7}, {%8,%9}, {%0,%1,%2,%3};"
        : "+f"(d[0]), "+f"(d[1]), "+f"(d[2]), "+f"(d[3])
        : "r"(a[0]), "r"(a[1]), "r"(a[2]), "r"(a[3]),
          "r"(b[0]), "r"(b[1]));
}

__device__ __forceinline__ uint32_t smem_u32(const void* p) {
    return (uint32_t)__cvta_generic_to_shared(p);
}

__device__ __forceinline__ void cp16(uint32_t saddr, const void* gptr) {
    asm volatile("cp.async.cg.shared.global [%0], [%1], 16;"
                 :: "r"(saddr), "l"(__cvta_generic_to_global(gptr)) : "memory");
}

#define CP_COMMIT()   asm volatile("cp.async.commit_group;" ::: "memory")
#define CP_WAIT_ALL() asm volatile("cp.async.wait_group 0;" ::: "memory")
#define CP_WAIT_1()   asm volatile("cp.async.wait_group 1;" ::: "memory")
#define BAR_GRP(id)   asm volatile("bar.sync %0, 128;" :: "r"(id) : "memory")

// split a float pair into packed bf16x2 hi and lo
__device__ __forceinline__ uint32_t pack_split(float x, float y, uint32_t& lo)
{
    __nv_bfloat16 hx = __float2bfloat16_rn(x);
    __nv_bfloat16 hy = __float2bfloat16_rn(y);
    __nv_bfloat162 hp(hx, hy);
    __nv_bfloat162 lp(__float2bfloat16_rn(x - __bfloat162float(hx)),
                      __float2bfloat16_rn(y - __bfloat162float(hy)));
    lo = *(uint32_t*)&lp;
    return *(uint32_t*)&hp;
}

// ---------------------------------------------------------------------------
// Prep: split x into bf16 hi/lo — 4x MLP version
// ---------------------------------------------------------------------------
__global__ __launch_bounds__(256)
void split_x_kernel(const float* __restrict__ x)
{
    const int base = blockIdx.x * 1024 + threadIdx.x;   // float4 index
    float4 v[4];
#pragma unroll
    for (int j = 0; j < 4; j++)
        v[j] = ((const float4*)x)[base + j * 256];

    __nv_bfloat162* ph = (__nv_bfloat162*)g_xh;
    __nv_bfloat162* pl = (__nv_bfloat162*)g_xl;
#pragma unroll
    for (int j = 0; j < 4; j++) {
        const int i = base + j * 256;
        __nv_bfloat16 h0 = __float2bfloat16_rn(v[j].x);
        __nv_bfloat16 h1 = __float2bfloat16_rn(v[j].y);
        __nv_bfloat16 h2 = __float2bfloat16_rn(v[j].z);
        __nv_bfloat16 h3 = __float2bfloat16_rn(v[j].w);
        __nv_bfloat16 l0 = __float2bfloat16_rn(v[j].x - __bfloat162float(h0));
        __nv_bfloat16 l1 = __float2bfloat16_rn(v[j].y - __bfloat162float(h1));
        __nv_bfloat16 l2 = __float2bfloat16_rn(v[j].z - __bfloat162float(h2));
        __nv_bfloat16 l3 = __float2bfloat16_rn(v[j].w - __bfloat162float(h3));
        ph[2 * i]     = __nv_bfloat162(h0, h1);
        ph[2 * i + 1] = __nv_bfloat162(h2, h3);
        pl[2 * i]     = __nv_bfloat162(l0, l1);
        pl[2 * i + 1] = __nv_bfloat162(l2, l3);
    }
}

// ---------------------------------------------------------------------------
// Prep: transpose + split W via smem tiles (coalesced both directions).
// W[k][n] (n contiguous) -> wt[mat][n][k] (k contiguous), hi/lo.
// Grid (NE/32, H/32, 3), 256 threads, 32x32 tile.
// ---------------------------------------------------------------------------
__global__ __launch_bounds__(256)
void split_w_kernel(const float* __restrict__ Wq,
                    const float* __restrict__ Wk,
                    const float* __restrict__ Wv)
{
    __shared__ float ts[32][33];
    const int mat = blockIdx.z;
    const float* W = (mat == 0) ? Wq : (mat == 1) ? Wk : Wv;
    const int tx = threadIdx.x & 31;
    const int ty = threadIdx.x >> 5;             // 0..7
    const int k0 = blockIdx.x * 32;
    const int n0 = blockIdx.y * 32;

#pragma unroll
    for (int i = 0; i < 4; i++)
        ts[ty + 8 * i][tx] = W[(size_t)(k0 + ty + 8 * i) * H + n0 + tx];
    __syncthreads();

    __nv_bfloat16* wh = g_wth + (size_t)mat * (H * NE);
    __nv_bfloat16* wl = g_wtl + (size_t)mat * (H * NE);
#pragma unroll
    for (int i = 0; i < 4; i++) {
        float w = ts[tx][ty + 8 * i];            // = W[k0+tx][n0+ty+8i]
        __nv_bfloat16 hi = __float2bfloat16_rn(w);
        __nv_bfloat16 lo = __float2bfloat16_rn(w - __bfloat162float(hi));
        size_t o = (size_t)(n0 + ty + 8 * i) * NE + k0 + tx;
        wh[o] = hi;
        wl[o] = lo;
    }
}

// ---------------------------------------------------------------------------
// QKV GEMM via mma.sync (bf16 hi/lo split, fp32 accum),
// cp.async DOUBLE-BUFFERED staging, ILP-ordered MMAs (R13 form, verbatim).
// mat==2 epilogue: in-kernel transpose+split of v -> g_vth/g_vtl.
// ---------------------------------------------------------------------------
#define KC      64
#define TSTRIDE 72
#define TILE_BF (128 * TSTRIDE)
#define GBUF_ELEMS (4 * TILE_BF)                 // one buffer: xh,xl,wh,wl
#define GEMM_SMEM_BYTES (2 * GBUF_ELEMS * 2)     // 147456

extern __shared__ __nv_bfloat16 gsm[];

__device__ __forceinline__ void gemm_stage(uint32_t sb, int buf, int m0,
                                           const __nv_bfloat16* wh_base,
                                           const __nv_bfloat16* wl_base,
                                           int k0, int tid)
{
    const uint32_t base = sb + buf * (GBUF_ELEMS * 2);
#pragma unroll
    for (int it = 0; it < 4; it++) {
        int idx = it * 256 + tid;
        int r  = idx >> 3;
        int c8 = (idx & 7) * 8;
        size_t xs = (size_t)(m0 + r) * NE + k0 + c8;
        size_t ws = (size_t)r * NE + k0 + c8;
        uint32_t dsto = (r * TSTRIDE + c8) * 2;
        cp16(base + 0 * TILE_BF * 2 + dsto, g_xh + xs);
        cp16(base + 1 * TILE_BF * 2 + dsto, g_xl + xs);
        cp16(base + 2 * TILE_BF * 2 + dsto, wh_base + ws);
        cp16(base + 3 * TILE_BF * 2 + dsto, wl_base + ws);
    }
}

__global__ __launch_bounds__(256)
void qkv_mma_kernel()
{
    const uint32_t sb = smem_u32(gsm);

    const int tid = threadIdx.x;
    const int wid = tid >> 5;
    const int lid = tid & 31;
    const int g   = lid >> 2;
    const int t   = lid & 3;

    const int m0  = blockIdx.x * 128;
    const int mat = blockIdx.y;
    const int wm  = (wid >> 1) * 32;
    const int wn  = (wid & 1) * 64;

    const __nv_bfloat16* wh_base = g_wth + (size_t)mat * (H * NE);
    const __nv_bfloat16* wl_base = g_wtl + (size_t)mat * (H * NE);

    float acc[2][8][4];
#pragma unroll
    for (int mi = 0; mi < 2; mi++)
#pragma unroll
        for (int ni = 0; ni < 8; ni++)
#pragma unroll
            for (int c = 0; c < 4; c++) acc[mi][ni][c] = 0.f;

    gemm_stage(sb, 0, m0, wh_base, wl_base, 0, tid);
    CP_COMMIT();

    for (int kc = 0; kc < 16; kc++) {
        if (kc < 15) {
            gemm_stage(sb, (kc + 1) & 1, m0, wh_base, wl_base, (kc + 1) * KC, tid);
            CP_COMMIT();
            CP_WAIT_1();
        } else {
            CP_WAIT_ALL();
        }
        __syncthreads();

        const __nv_bfloat16* Axh = gsm + (kc & 1) * GBUF_ELEMS;
        const __nv_bfloat16* Axl = Axh + TILE_BF;
        const __nv_bfloat16* Bwh = Axl + TILE_BF;
        const __nv_bfloat16* Bwl = Bwh + TILE_BF;

#pragma unroll
        for (int ks = 0; ks < 4; ks++) {
            const int kk = ks * 16;
            uint32_t ah[2][4], al[2][4];
#pragma unroll
            for (int mi = 0; mi < 2; mi++) {
                int r = wm + mi * 16;
                ah[mi][0] = *(const uint32_t*)&Axh[(r + g    ) * TSTRIDE + kk + 2 * t    ];
                ah[mi][1] = *(const uint32_t*)&Axh[(r + g + 8) * TSTRIDE + kk + 2 * t    ];
                ah[mi][2] = *(const uint32_t*)&Axh[(r + g    ) * TSTRIDE + kk + 2 * t + 8];
                ah[mi][3] = *(const uint32_t*)&Axh[(r + g + 8) * TSTRIDE + kk + 2 * t + 8];
                al[mi][0] = *(const uint32_t*)&Axl[(r + g    ) * TSTRIDE + kk + 2 * t    ];
                al[mi][1] = *(const uint32_t*)&Axl[(r + g + 8) * TSTRIDE + kk + 2 * t    ];
                al[mi][2] = *(const uint32_t*)&Axl[(r + g    ) * TSTRIDE + kk + 2 * t + 8];
                al[mi][3] = *(const uint32_t*)&Axl[(r + g + 8) * TSTRIDE + kk + 2 * t + 8];
            }
            // block-of-4 n-tiles: 8 independent MMAs between accumulator reuse
#pragma unroll
            for (int nb = 0; nb < 2; nb++) {
                uint32_t bh[4][2], bl[4][2];
#pragma unroll
                for (int j = 0; j < 4; j++) {
                    int nr = wn + (nb * 4 + j) * 8 + g;
                    bh[j][0] = *(const uint32_t*)&Bwh[nr * TSTRIDE + kk + 2 * t    ];
                    bh[j][1] = *(const uint32_t*)&Bwh[nr * TSTRIDE + kk + 2 * t + 8];
                    bl[j][0] = *(const uint32_t*)&Bwl[nr * TSTRIDE + kk + 2 * t    ];
                    bl[j][1] = *(const uint32_t*)&Bwl[nr * TSTRIDE + kk + 2 * t + 8];
                }
#pragma unroll
                for (int j = 0; j < 4; j++)
#pragma unroll
                    for (int mi = 0; mi < 2; mi++)
                        mma16816(acc[mi][nb * 4 + j], ah[mi], bh[j]);
#pragma unroll
                for (int j = 0; j < 4; j++)
#pragma unroll
                    for (int mi = 0; mi < 2; mi++)
                        mma16816(acc[mi][nb * 4 + j], ah[mi], bl[j]);
#pragma unroll
                for (int j = 0; j < 4; j++)
#pragma unroll
                    for (int mi = 0; mi < 2; mi++)
                        mma16816(acc[mi][nb * 4 + j], al[mi], bh[j]);
            }
        }
        __syncthreads();
    }

    // epilogue
    if (mat == 2) {
        // stage v tile (fp32) to smem, then transposed+split write to g_vt*
        float* ep = (float*)gsm;                 // 128 x 132 fp32 = 66 KB
#pragma unroll
        for (int mi = 0; mi < 2; mi++)
#pragma unroll
            for (int ni = 0; ni < 8; ni++) {
                int lr = wm + mi * 16 + g;
                int c  = wn + ni * 8 + 2 * t;
                ep[lr * 132 + c]           = acc[mi][ni][0];
                ep[lr * 132 + c + 1]       = acc[mi][ni][1];
                ep[(lr + 8) * 132 + c]     = acc[mi][ni][2];
                ep[(lr + 8) * 132 + c + 1] = acc[mi][ni][3];
            }
        __syncthreads();

        const int b  = m0 >> 11;                 // batch
        const int t0 = m0 & 2047;                // t offset within batch
        const int h   = tid & 127;
        const int sel = tid >> 7;                // 0 = hi, 1 = lo
        __nv_bfloat16* dst = sel ? g_vtl : g_vth;
        __nv_bfloat16* drow = dst + ((size_t)b * H + h) * T + t0;
#pragma unroll
        for (int j8 = 0; j8 < 16; j8++) {
            union { __nv_bfloat16 bh[8]; uint4 u4; } tmp;
#pragma unroll
            for (int u = 0; u < 8; u++) {
                float v = ep[(j8 * 8 + u) * 132 + h];
                __nv_bfloat16 hi = __float2bfloat16_rn(v);
                tmp.bh[u] = sel ? __float2bfloat16_rn(v - __bfloat162float(hi))
                                : hi;
            }
            *(uint4*)&drow[j8 * 8] = tmp.u4;
        }
    } else {
        const float sc = (mat == 0) ? 0.03125f : 1.0f;
        __nv_bfloat16* dh = (mat == 0) ? g_qh : g_kh;
        __nv_bfloat16* dl = (mat == 0) ? g_ql : g_kl;
#pragma unroll
        for (int mi = 0; mi < 2; mi++)
#pragma unroll
            for (int ni = 0; ni < 8; ni++) {
                int r0 = m0 + wm + mi * 16 + g;
                int c  = wn + ni * 8 + 2 * t;
                uint32_t lo0, lo1;
                uint32_t hi0 = pack_split(acc[mi][ni][0] * sc, acc[mi][ni][1] * sc, lo0);
                uint32_t hi1 = pack_split(acc[mi][ni][2] * sc, acc[mi][ni][3] * sc, lo1);
                *(uint32_t*)&dh[(size_t)r0 * H + c]       = hi0;
                *(uint32_t*)&dl[(size_t)r0 * H + c]       = lo0;
                *(uint32_t*)&dh[(size_t)(r0 + 8) * H + c] = hi1;
                *(uint32_t*)&dl[(size_t)(r0 + 8) * H + c] = lo1;
            }
    }
}

// ---------------------------------------------------------------------------
// Flash attention: split-K across 2 warp groups (256 threads), plain-LDS
// frag loads, ILP-ordered MMAs (R13 form, verbatim). Group wg handles
// kv-chunks kb ≡ wg (mod 2) in its own buffer; states merged at the end.
// Grid (16, 8), paired q-tiles.
// ---------------------------------------------------------------------------
#define KSTRIDE 136
#define VSTRIDE 72
#define AT_SKH  0
#define AT_SKL  (64 * KSTRIDE)
#define AT_SVH  (2 * 64 * KSTRIDE)
#define AT_SVL  (2 * 64 * KSTRIDE + 128 * VSTRIDE)
#define AT_BUF_ELEMS (2 * 64 * KSTRIDE + 2 * 128 * VSTRIDE)   // 35840
#define AT_SMEM_BYTES (2 * AT_BUF_ELEMS * 2)                  // 143360
#define MSTRIDE 69                                            // merge stride

extern __shared__ __nv_bfloat16 att_sm[];

__device__ __forceinline__ void stage_kv(uint32_t smbase, int buf, int b,
                                         int kv0, int t128)
{
    const __nv_bfloat16* kh  = g_kh  + ((size_t)b * T + kv0) * H;
    const __nv_bfloat16* kl  = g_kl  + ((size_t)b * T + kv0) * H;
    const __nv_bfloat16* vth = g_vth + (size_t)b * H * T + kv0;
    const __nv_bfloat16* vtl = g_vtl + (size_t)b * H * T + kv0;
    const uint32_t base = smbase + buf * (AT_BUF_ELEMS * 2);
#pragma unroll
    for (int it = 0; it < 8; it++) {
        int idx = it * 128 + t128;
        int r  = idx >> 4;
        int c8 = (idx & 15) * 8;
        cp16(base + (AT_SKH + r * KSTRIDE + c8) * 2, kh + (size_t)r * H + c8);
        cp16(base + (AT_SKL + r * KSTRIDE + c8) * 2, kl + (size_t)r * H + c8);
    }
#pragma unroll
    for (int it = 0; it < 8; it++) {
        int idx = it * 128 + t128;
        int r  = idx >> 3;
        int c8 = (idx & 7) * 8;
        cp16(base + (AT_SVH + r * VSTRIDE + c8) * 2, vth + (size_t)r * T + c8);
        cp16(base + (AT_SVL + r * VSTRIDE + c8) * 2, vtl + (size_t)r * T + c8);
    }
}

__global__ __launch_bounds__(256, 1)
void attn_mma_kernel(float* __restrict__ out)
{
    __nv_bfloat16* sm = att_sm;
    const uint32_t smbase = smem_u32(att_sm);
    const int tid  = threadIdx.x;
    const int wg   = tid >> 7;           // warp group 0/1
    const int t128 = tid & 127;
    const int w    = (tid >> 5) & 3;     // warp within group
    const int lid  = tid & 31;
    const int g    = lid >> 2;
    const int t    = lid & 3;
    const int barid = 1 + wg;

    const int pa = blockIdx.x;
    const int b  = blockIdx.y;

#pragma unroll 1
    for (int half = 0; half < 2; half++) {
        const int qb = half ? pa : 31 - pa;
        const int q0 = qb * 64;

        // ---- persistent Q fragments (hi/lo); both groups load same rows ----
        uint32_t qh[8][4], ql[8][4];
        {
            const __nv_bfloat16* qgh = g_qh + ((size_t)b * T + q0 + w * 16) * H;
            const __nv_bfloat16* qgl = g_ql + ((size_t)b * T + q0 + w * 16) * H;
#pragma unroll
            for (int kc = 0; kc < 8; kc++) {
                int cb = kc * 16 + 2 * t;
                qh[kc][0] = *(const uint32_t*)&qgh[(size_t)g       * H + cb];
                qh[kc][1] = *(const uint32_t*)&qgh[(size_t)(g + 8) * H + cb];
                qh[kc][2] = *(const uint32_t*)&qgh[(size_t)g       * H + cb + 8];
                qh[kc][3] = *(const uint32_t*)&qgh[(size_t)(g + 8) * H + cb + 8];
                ql[kc][0] = *(const uint32_t*)&qgl[(size_t)g       * H + cb];
                ql[kc][1] = *(const uint32_t*)&qgl[(size_t)(g + 8) * H + cb];
                ql[kc][2] = *(const uint32_t*)&qgl[(size_t)g       * H + cb + 8];
                ql[kc][3] = *(const uint32_t*)&qgl[(size_t)(g + 8) * H + cb + 8];
            }
        }

        float o[16][4];
#pragma unroll
        for (int nt = 0; nt < 16; nt++)
#pragma unroll
            for (int c = 0; c < 4; c++) o[nt][c] = 0.f;
        float m0 = -1e30f, m1 = -1e30f, l0 = 0.f, l1 = 0.f;

        const int bo = wg * AT_BUF_ELEMS;

        if (wg <= qb) {
            stage_kv(smbase, wg, b, wg * 64, t128);
            CP_COMMIT();
        }

#pragma unroll 1
        for (int kb = wg; kb <= qb; kb += 2) {
            CP_WAIT_ALL();
            BAR_GRP(barid);

            // ---- S = Q K^T, ILP-ordered: blocks of 4 n-tiles ----
            float sC[8][4];
#pragma unroll
            for (int nt = 0; nt < 8; nt++)
#pragma unroll
                for (int c = 0; c < 4; c++) sC[nt][c] = 0.f;

#pragma unroll
            for (int kc = 0; kc < 8; kc++) {
                const int kk = kc * 16 + 2 * t;
#pragma unroll
                for (int nb = 0; nb < 2; nb++) {
                    uint32_t bh[4][2], bl[4][2];
#pragma unroll
                    for (int j = 0; j < 4; j++) {
                        const int n = (nb * 4 + j) * 8 + g;
                        bh[j][0] = *(const uint32_t*)&sm[bo + AT_SKH + n * KSTRIDE + kk];
                        bh[j][1] = *(const uint32_t*)&sm[bo + AT_SKH + n * KSTRIDE + kk + 8];
                        bl[j][0] = *(const uint32_t*)&sm[bo + AT_SKL + n * KSTRIDE + kk];
                        bl[j][1] = *(const uint32_t*)&sm[bo + AT_SKL + n * KSTRIDE + kk + 8];
                    }
#pragma unroll
                    for (int j = 0; j < 4; j++)
                        mma16816(sC[nb * 4 + j], qh[kc], bh[j]);
#pragma unroll
                    for (int j = 0; j < 4; j++)
                        mma16816(sC[nb * 4 + j], qh[kc], bl[j]);
#pragma unroll
                    for (int j = 0; j < 4; j++)
                        mma16816(sC[nb * 4 + j], ql[kc], bh[j]);
                }
            }

            // ---- causal mask (diagonal chunk only) ----
            if (kb == qb) {
                const int rl0 = w * 16 + g;
                const int rl1 = rl0 + 8;
#pragma unroll
                for (int nt = 0; nt < 8; nt++) {
                    int c0 = nt * 8 + 2 * t;
                    if (c0     > rl0) sC[nt][0] = -1e30f;
                    if (c0 + 1 > rl0) sC[nt][1] = -1e30f;
                    if (c0     > rl1) sC[nt][2] = -1e30f;
                    if (c0 + 1 > rl1) sC[nt][3] = -1e30f;
                }
            }

            // ---- online softmax ----
            float mx0 = -1e30f, mx1 = -1e30f;
#pragma unroll
            for (int nt = 0; nt < 8; nt++) {
                mx0 = fmaxf(mx0, fmaxf(sC[nt][0], sC[nt][1]));
                mx1 = fmaxf(mx1, fmaxf(sC[nt][2], sC[nt][3]));
            }
            mx0 = fmaxf(mx0, __shfl_xor_sync(0xffffffffu, mx0, 1));
            mx0 = fmaxf(mx0, __shfl_xor_sync(0xffffffffu, mx0, 2));
            mx1 = fmaxf(mx1, __shfl_xor_sync(0xffffffffu, mx1, 1));
            mx1 = fmaxf(mx1, __shfl_xor_sync(0xffffffffu, mx1, 2));

            float mn0 = fmaxf(m0, mx0), mn1 = fmaxf(m1, mx1);
            float a0 = __expf(m0 - mn0), a1 = __expf(m1 - mn1);
            m0 = mn0; m1 = mn1;

            float rs0 = 0.f, rs1 = 0.f;
#pragma unroll
            for (int nt = 0; nt < 8; nt++) {
                sC[nt][0] = __expf(sC[nt][0] - mn0); rs0 += sC[nt][0];
                sC[nt][1] = __expf(sC[nt][1] - mn0); rs0 += sC[nt][1];
                sC[nt][2] = __expf(sC[nt][2] - mn1); rs1 += sC[nt][2];
                sC[nt][3] = __expf(sC[nt][3] - mn1); rs1 += sC[nt][3];
            }
            rs0 += __shfl_xor_sync(0xffffffffu, rs0, 1);
            rs0 += __shfl_xor_sync(0xffffffffu, rs0, 2);
            rs1 += __shfl_xor_sync(0xffffffffu, rs1, 1);
            rs1 += __shfl_xor_sync(0xffffffffu, rs1, 2);
            l0 = l0 * a0 + rs0;
            l1 = l1 * a1 + rs1;

#pragma unroll
            for (int nt = 0; nt < 16; nt++) {
                o[nt][0] *= a0; o[nt][1] *= a0;
                o[nt][2] *= a1; o[nt][3] *= a1;
            }

            // ---- pack P C-frags -> A-frags (hi/lo) ----
            uint32_t pah[4][4], pal[4][4];
#pragma unroll
            for (int kc = 0; kc < 4; kc++) {
                pah[kc][0] = pack_split(sC[2 * kc][0],     sC[2 * kc][1],     pal[kc][0]);
                pah[kc][1] = pack_split(sC[2 * kc][2],     sC[2 * kc][3],     pal[kc][1]);
                pah[kc][2] = pack_split(sC[2 * kc + 1][0], sC[2 * kc + 1][1], pal[kc][2]);
                pah[kc][3] = pack_split(sC[2 * kc + 1][2], sC[2 * kc + 1][3], pal[kc][3]);
            }

            // ---- O += P V, ILP-ordered: blocks of 4 n-tiles ----
#pragma unroll
            for (int kc = 0; kc < 4; kc++) {
                const int kk = kc * 16 + 2 * t;
#pragma unroll
                for (int nb = 0; nb < 4; nb++) {
                    uint32_t vh[4][2], vl[4][2];
#pragma unroll
                    for (int j = 0; j < 4; j++) {
                        const int n = (nb * 4 + j) * 8 + g;
                        vh[j][0] = *(const uint32_t*)&sm[bo + AT_SVH + n * VSTRIDE + kk];
                        vh[j][1] = *(const uint32_t*)&sm[bo + AT_SVH + n * VSTRIDE + kk + 8];
                        vl[j][0] = *(const uint32_t*)&sm[bo + AT_SVL + n * VSTRIDE + kk];
                        vl[j][1] = *(const uint32_t*)&sm[bo + AT_SVL + n * VSTRIDE + kk + 8];
                    }
#pragma unroll
                    for (int j = 0; j < 4; j++)
                        mma16816(o[nb * 4 + j], pah[kc], vh[j]);
#pragma unroll
                    for (int j = 0; j < 4; j++)
                        mma16816(o[nb * 4 + j], pah[kc], vl[j]);
#pragma unroll
                    for (int j = 0; j < 4; j++)
                        mma16816(o[nb * 4 + j], pal[kc], vh[j]);
                }
            }

            BAR_GRP(barid);   // group done reading buffer
            if (kb + 2 <= qb) {
                stage_kv(smbase, wg, b, (kb + 2) * 64, t128);
                CP_COMMIT();
            }
        }

        // ---- merge the two groups' states ----
        __syncthreads();                         // all KV traffic done
        float* ms = (float*)att_sm;              // aliases KV buffers
        if (wg == 1) {
            const int base = t128 * MSTRIDE;
#pragma unroll
            for (int nt = 0; nt < 16; nt++)
#pragma unroll
                for (int c = 0; c < 4; c++)
                    ms[base + nt * 4 + c] = o[nt][c];
            ms[base + 64] = m0;
            ms[base + 65] = l0;
            ms[base + 66] = m1;
            ms[base + 67] = l1;
        }
        __syncthreads();
        if (wg == 0) {
            const int base = t128 * MSTRIDE;
            float sm0 = ms[base + 64], sl0 = ms[base + 65];
            float sm1 = ms[base + 66], sl1 = ms[base + 67];
            float M0 = fmaxf(m0, sm0), M1 = fmaxf(m1, sm1);
            float a0 = __expf(m0 - M0), b0 = __expf(sm0 - M0);
            float a1 = __expf(m1 - M1), b1 = __expf(sm1 - M1);
            float inv0 = 1.0f / (l0 * a0 + sl0 * b0);
            float inv1 = 1.0f / (l1 * a1 + sl1 * b1);

            float* og = out + ((size_t)b * T + q0 + w * 16) * H;
#pragma unroll
            for (int nt = 0; nt < 16; nt++) {
                int c = nt * 8 + 2 * t;
                float r00 = (o[nt][0] * a0 + ms[base + nt * 4 + 0] * b0) * inv0;
                float r01 = (o[nt][1] * a0 + ms[base + nt * 4 + 1] * b0) * inv0;
                float r10 = (o[nt][2] * a1 + ms[base + nt * 4 + 2] * b1) * inv1;
                float r11 = (o[nt][3] * a1 + ms[base + nt * 4 + 3] * b1) * inv1;
                *(float2*)&og[(size_t)g * H + c]       = make_float2(r00, r01);
                *(float2*)&og[(size_t)(g + 8) * H + c] = make_float2(r10, r11);
            }
        }
        __syncthreads();                         // merge reads done
    }
}

// ---------------------------------------------------------------------------
extern "C" void kernel_launch(void* const* d_in, const int* in_sizes, int n_in,
                              void* d_out, int out_size)
{
    (void)in_sizes; (void)n_in; (void)out_size;
    const float* x  = (const float*)d_in[0];
    const float* Wq = (const float*)d_in[1];
    const float* Wk = (const float*)d_in[2];
    const float* Wv = (const float*)d_in[3];
    float* out = (float*)d_out;

    split_x_kernel<<<BT * NE / 4 / 1024, 256>>>(x);

    dim3 gw(NE / 32, H / 32, 3);
    split_w_kernel<<<gw, 256>>>(Wq, Wk, Wv);

    cudaFuncSetAttribute(qkv_mma_kernel,
                         cudaFuncAttributeMaxDynamicSharedMemorySize, GEMM_SMEM_BYTES);
    dim3 g1(BT / 128, 3);
    qkv_mma_kernel<<<g1, 256, GEMM_SMEM_BYTES>>>();

    cudaFuncSetAttribute(attn_mma_kernel,
                         cudaFuncAttributeMaxDynamicSharedMemorySize, AT_SMEM_BYTES);
    dim3 g2(16, NB);
    attn_mma_kernel<<<g2, 256, AT_SMEM_BYTES>>>(out);
}